// round 6
// baseline (speedup 1.0000x reference)
#include <cuda_runtime.h>

// Problem constants (fixed by the dataset)
#define BATCH 32
#define HW    196      // 14*14 spatial positions
#define C     512      // input channels
#define D     8192     // sketch / output dimension
#define KT    14       // K-chunk for shared tiles (196 = 14*14)
#define BCH   4        // batches per GEMM CTA

typedef unsigned long long ull;

// Scratch: M_t[c1][c2][b] = s1[c1]*s2[c2] * sum_k X1[b,k,c1]*X2[b,k,c2]
// Batch-minor so the phase-2 gather (lane = batch) is one coalesced 128B load.
__device__ __align__(16) float M_t[(size_t)C * C * BATCH];   // 33.5 MB
__device__ int          g_hist[D];
__device__ int          g_off[D + 1];
__device__ int          g_cursor[D];
__device__ unsigned int g_pairs[C * C];    // entry = c1*512 + c2, bucket-sorted

// Packed fp32x2 FMA (Blackwell)
#define FMA2(acc, a2, b2) \
    asm("fma.rn.f32x2 %0, %1, %2, %0;" : "+l"(acc) : "l"(a2), "l"(b2))
#define PACK2(o, lo, hi) \
    asm("mov.b64 %0, {%1, %2};" : "=l"(o) : "f"(lo), "f"(hi))
#define UNPACK2(lo, hi, in) \
    asm("mov.b64 {%0, %1}, %2;" : "=f"(lo), "=f"(hi) : "l"(in))

// ---------- phase 0: bucket the (c1,c2) pairs by hash ----------

__global__ void k_zero_hist()
{
    int i = blockIdx.x * blockDim.x + threadIdx.x;
    if (i < D) g_hist[i] = 0;
}

// 8192 threads: c1 = gid>>4, c2 chunk of 32
__global__ void k_count(const int* __restrict__ h1, const int* __restrict__ h2)
{
    int gid = blockIdx.x * blockDim.x + threadIdx.x;
    int c1 = gid >> 4;
    int c2_0 = (gid & 15) * 32;
    int hv = h1[c1];
    #pragma unroll
    for (int j = 0; j < 32; j++) {
        int d = (hv + h2[c2_0 + j]) & (D - 1);
        atomicAdd(&g_hist[d], 1);
    }
}

// single CTA, 256 threads: exclusive prefix over 8192 buckets
__global__ void k_scan()
{
    __shared__ int part[256];
    int t = threadIdx.x;
    int local[32];
    int s = 0;
    #pragma unroll
    for (int i = 0; i < 32; i++) { local[i] = s; s += g_hist[t * 32 + i]; }
    part[t] = s;
    __syncthreads();
    for (int off = 1; off < 256; off <<= 1) {
        int v = (t >= off) ? part[t - off] : 0;
        __syncthreads();
        part[t] += v;
        __syncthreads();
    }
    int base = part[t] - s;        // exclusive prefix of this 32-chunk
    #pragma unroll
    for (int i = 0; i < 32; i++) {
        int o = base + local[i];
        g_off[t * 32 + i]    = o;
        g_cursor[t * 32 + i] = o;
    }
    if (t == 255) g_off[D] = part[255];
}

__global__ void k_fill(const int* __restrict__ h1, const int* __restrict__ h2)
{
    int gid = blockIdx.x * blockDim.x + threadIdx.x;
    int c1 = gid >> 4;
    int c2_0 = (gid & 15) * 32;
    int hv = h1[c1];
    #pragma unroll
    for (int j = 0; j < 32; j++) {
        int c2 = c2_0 + j;
        int d = (hv + h2[c2]) & (D - 1);
        int pos = atomicAdd(&g_cursor[d], 1);
        g_pairs[pos] = (unsigned int)(c1 * C + c2);
    }
}

// ---------- phase 1: batched GEMM -> M_t (no atomics) ----------
// grid (8, 8, 8): c1 tile 64, c2 tile 64, batch chunk 4. 256 threads,
// 4x4 products x 4 batches per thread; batch pairs ride the fp32x2 lanes.
__global__ __launch_bounds__(256, 2)
void k_gemm(const float* __restrict__ x1, const float* __restrict__ x2,
            const float* __restrict__ s1, const float* __restrict__ s2)
{
    __shared__ float X1s[KT][64][BCH];   // [kk][channel][batch]
    __shared__ float X2s[KT][64][BCH];

    const int tid = threadIdx.x;
    const int tx  = tid & 15;            // c2 quad
    const int ty  = tid >> 4;            // c1 quad
    const int c1_base = blockIdx.x * 64;
    const int c2_base = blockIdx.y * 64;
    const int bbase   = blockIdx.z * BCH;

    const int lc  = tid & 63;
    const int kks = tid >> 6;
    const float s1l = __ldg(&s1[c1_base + lc]);
    const float s2l = __ldg(&s2[c2_base + lc]);

    const float* p1base = x1 + (size_t)bbase * HW * C + c1_base + lc;
    const float* p2base = x2 + (size_t)bbase * HW * C + c2_base + lc;
    const size_t bstr = (size_t)HW * C;

    ull acc[4][4][2];                    // fp32x2 over batch pairs
    #pragma unroll
    for (int i = 0; i < 4; i++)
        #pragma unroll
        for (int j = 0; j < 4; j++) { acc[i][j][0] = 0ULL; acc[i][j][1] = 0ULL; }

    for (int k0 = 0; k0 < HW; k0 += KT) {
        __syncthreads();
        #pragma unroll
        for (int n = 0; n < 4; ++n) {
            int kk = kks + 4 * n;
            if (kk < KT) {
                const float* p1 = p1base + (size_t)(k0 + kk) * C;
                const float* p2 = p2base + (size_t)(k0 + kk) * C;
                float4 v1, v2;
                v1.x = p1[0]        * s1l;  v1.y = p1[bstr]     * s1l;
                v1.z = p1[2 * bstr] * s1l;  v1.w = p1[3 * bstr] * s1l;
                v2.x = p2[0]        * s2l;  v2.y = p2[bstr]     * s2l;
                v2.z = p2[2 * bstr] * s2l;  v2.w = p2[3 * bstr] * s2l;
                *(float4*)&X1s[kk][lc][0] = v1;
                *(float4*)&X2s[kk][lc][0] = v2;
            }
        }
        __syncthreads();

        #pragma unroll
        for (int kk = 0; kk < KT; ++kk) {
            ull a2[4][2], b2[4][2];
            #pragma unroll
            for (int i = 0; i < 4; i++) {
                float4 av = *(const float4*)&X1s[kk][ty * 4 + i][0];
                PACK2(a2[i][0], av.x, av.y);
                PACK2(a2[i][1], av.z, av.w);
            }
            #pragma unroll
            for (int j = 0; j < 4; j++) {
                float4 bv = *(const float4*)&X2s[kk][tx * 4 + j][0];
                PACK2(b2[j][0], bv.x, bv.y);
                PACK2(b2[j][1], bv.z, bv.w);
            }
            #pragma unroll
            for (int i = 0; i < 4; i++)
                #pragma unroll
                for (int j = 0; j < 4; j++) {
                    FMA2(acc[i][j][0], a2[i][0], b2[j][0]);
                    FMA2(acc[i][j][1], a2[i][1], b2[j][1]);
                }
        }
    }

    // plain coalesced-ish stores, 16B per product vector
    #pragma unroll
    for (int i = 0; i < 4; i++) {
        int c1 = c1_base + ty * 4 + i;
        #pragma unroll
        for (int j = 0; j < 4; j++) {
            int c2 = c2_base + tx * 4 + j;
            float4 v;
            UNPACK2(v.x, v.y, acc[i][j][0]);
            UNPACK2(v.z, v.w, acc[i][j][1]);
            *(float4*)&M_t[((size_t)c1 * C + c2) * BATCH + bbase] = v;
        }
    }
}

// ---------- phase 2: gather-reduce per bucket (no atomics) ----------
// warp per bucket, lane = batch. Each pair: one coalesced 128B load.
__global__ __launch_bounds__(256)
void k_gather(float* __restrict__ out)
{
    const int lane = threadIdx.x & 31;
    const int d = blockIdx.x * 8 + (threadIdx.x >> 5);

    const int pstart = g_off[d];
    const int pend   = g_off[d + 1];

    float acc = 0.0f;
    for (int p = pstart; p < pend; ++p) {
        unsigned int entry = g_pairs[p];              // warp-uniform
        acc += M_t[(size_t)entry * BATCH + lane];     // coalesced 128B
    }
    out[(size_t)lane * D + d] = acc;
}

extern "C" void kernel_launch(void* const* d_in, const int* in_sizes, int n_in,
                              void* d_out, int out_size)
{
    const float* x1 = (const float*)d_in[0];   // bottom1 [32,14,14,512]
    const float* x2 = (const float*)d_in[1];   // bottom2 [32,14,14,512]
    const float* s1 = (const float*)d_in[2];   // rand_s_1 [512]
    const float* s2 = (const float*)d_in[3];   // rand_s_2 [512]
    const int*   h1 = (const int*)d_in[4];     // rand_h_1 [512]
    const int*   h2 = (const int*)d_in[5];     // rand_h_2 [512]
    float* out = (float*)d_out;                // [32, 8192] float32

    // bucket the sparse scatter pattern (fixed per launch inputs)
    k_zero_hist<<<D / 256, 256>>>();
    k_count<<<32, 256>>>(h1, h2);              // 8192 threads
    k_scan<<<1, 256>>>();
    k_fill<<<32, 256>>>(h1, h2);

    // batched GEMM into M_t
    dim3 grid(C / 64, C / 64, BATCH / BCH);    // (8, 8, 8) = 512 CTAs
    k_gemm<<<grid, 256>>>(x1, x2, s1, s2);

    // per-bucket gather-reduce into the output
    k_gather<<<D / 8, 256>>>(out);
}

// round 7
// speedup vs baseline: 1.8346x; 1.8346x over previous
#include <cuda_runtime.h>

// Problem constants (fixed by the dataset)
#define BATCH 32
#define HW    196      // 14*14 spatial positions
#define C     512      // input channels
#define D     8192     // sketch / output dimension
#define KT    14       // K-chunk for shared tiles (196 = 14*14)
#define BCH   4        // batches per GEMM CTA

typedef unsigned long long ull;

// Scratch: M_t[c1][c2][b] = s1[c1]*s2[c2] * sum_k X1[b,k,c1]*X2[b,k,c2]
// Batch-minor: phase-2 gather (lane = batch) reads one coalesced 128B line.
__device__ __align__(16) float M_t[(size_t)C * C * BATCH];   // 33.5 MB
__device__ int          g_hist[D];
__device__ int          g_off[D + 1];
__device__ int          g_cursor[D];
__device__ unsigned int g_pairs[C * C];    // entry = c1*512 + c2, bucket-sorted

// Packed fp32x2 FMA (Blackwell)
#define FMA2(acc, a2, b2) \
    asm("fma.rn.f32x2 %0, %1, %2, %0;" : "+l"(acc) : "l"(a2), "l"(b2))

union V4 { float4 f; ull u[2]; };

// ---------- phase 0: bucket the (c1,c2) pairs by hash ----------

__global__ void k_zero_hist()
{
    int i = blockIdx.x * blockDim.x + threadIdx.x;
    if (i < D) g_hist[i] = 0;
}

// one thread per (c1,c2) pair: 262144 independent atomics (throughput-bound)
__global__ void k_count(const int* __restrict__ h1, const int* __restrict__ h2)
{
    int gid = blockIdx.x * blockDim.x + threadIdx.x;
    int d = (h1[gid >> 9] + h2[gid & (C - 1)]) & (D - 1);
    atomicAdd(&g_hist[d], 1);
}

// single CTA, 256 threads: exclusive prefix over 8192 buckets
__global__ void k_scan()
{
    __shared__ int part[256];
    int t = threadIdx.x;
    int local[32];
    int s = 0;
    #pragma unroll
    for (int i = 0; i < 32; i++) { local[i] = s; s += g_hist[t * 32 + i]; }
    part[t] = s;
    __syncthreads();
    for (int off = 1; off < 256; off <<= 1) {
        int v = (t >= off) ? part[t - off] : 0;
        __syncthreads();
        part[t] += v;
        __syncthreads();
    }
    int base = part[t] - s;        // exclusive prefix of this 32-chunk
    #pragma unroll
    for (int i = 0; i < 32; i++) {
        int o = base + local[i];
        g_off[t * 32 + i]    = o;
        g_cursor[t * 32 + i] = o;
    }
    if (t == 255) g_off[D] = part[255];
}

__global__ void k_fill(const int* __restrict__ h1, const int* __restrict__ h2)
{
    int gid = blockIdx.x * blockDim.x + threadIdx.x;
    int c1 = gid >> 9, c2 = gid & (C - 1);
    int d = (h1[c1] + h2[c2]) & (D - 1);
    int pos = atomicAdd(&g_cursor[d], 1);
    g_pairs[pos] = (unsigned int)(c1 * C + c2);
}

// ---------- phase 1: batched GEMM -> M_t (no atomics) ----------
// Tile: c1 128 x c2 32 x batch 4. grid (4, 16, 8) = 512 CTAs, 256 threads.
// Thread (tx = tid&7 -> c2, ty = tid>>3 -> c1): 4 c1 x 4 c2 x 4 batches.
// Batch pairs ride the fp32x2 lanes via float4 bit-aliasing (no PACK ops).
// All LDS/STS conflict-free: fragment loads are 16B-stride across lanes.
__global__ __launch_bounds__(256, 2)
void k_gemm(const float* __restrict__ x1, const float* __restrict__ x2,
            const float* __restrict__ s1, const float* __restrict__ s2)
{
    __shared__ float X1s[KT][128 * BCH];   // [kk][c1*4 + b]  28 KB
    __shared__ float X2s[KT][32 * BCH];    // [kk][c2*4 + b]   7 KB

    const int tid = threadIdx.x;
    const int tx  = tid & 7;             // c2 lane
    const int ty  = tid >> 3;            // c1 lane (0..31)
    const int c1_base = blockIdx.x * 128;
    const int c2_base = blockIdx.y * 32;
    const int bbase   = blockIdx.z * BCH;

    const size_t bstr = (size_t)HW * C;  // batch stride in elements

    // X1 loader: idx = tid + 256n (n=0..6), c1 = idx&127 (constant/thread)
    const int   l1c = tid & 127;
    const float s1l = __ldg(&s1[c1_base + l1c]);
    // X2 loader: idx = tid + 256n (n=0..1), c2 = idx&31 (constant/thread)
    const int   l2c = tid & 31;
    const float s2l = __ldg(&s2[c2_base + l2c]);

    const float* p1base = x1 + (size_t)bbase * bstr + c1_base + l1c;
    const float* p2base = x2 + (size_t)bbase * bstr + c2_base + l2c;

    ull acc[4][4][2];                    // [c1 i][c2 j][batch pair]
    #pragma unroll
    for (int i = 0; i < 4; i++)
        #pragma unroll
        for (int j = 0; j < 4; j++) { acc[i][j][0] = 0ULL; acc[i][j][1] = 0ULL; }

    for (int k0 = 0; k0 < HW; k0 += KT) {
        __syncthreads();
        // X1 tile: 14*128 (kk,c1) slots, 4 batches each -> 7 float4/thread
        #pragma unroll
        for (int n = 0; n < 7; ++n) {
            int idx = tid + 256 * n;
            int kk  = idx >> 7;
            const float* p = p1base + (size_t)(k0 + kk) * C;
            float4 v;
            v.x = p[0]        * s1l;  v.y = p[bstr]     * s1l;
            v.z = p[2 * bstr] * s1l;  v.w = p[3 * bstr] * s1l;
            *(float4*)&X1s[kk][l1c * BCH] = v;     // 16B lane stride: N=1
        }
        // X2 tile: 14*32 slots -> 448 float4, 2 rounds (2nd partial)
        #pragma unroll
        for (int n = 0; n < 2; ++n) {
            int idx = tid + 256 * n;
            if (idx < KT * 32) {
                int kk = idx >> 5;
                const float* p = p2base + (size_t)(k0 + kk) * C;
                float4 v;
                v.x = p[0]        * s2l;  v.y = p[bstr]     * s2l;
                v.z = p[2 * bstr] * s2l;  v.w = p[3 * bstr] * s2l;
                *(float4*)&X2s[kk][l2c * BCH] = v;
            }
        }
        __syncthreads();

        #pragma unroll
        for (int kk = 0; kk < KT; ++kk) {
            V4 a[4], b[4];
            #pragma unroll
            for (int i = 0; i < 4; i++)    // c1 = ty + 32i: 16B lane stride
                a[i].f = *(const float4*)&X1s[kk][(ty + 32 * i) * BCH];
            #pragma unroll
            for (int j = 0; j < 4; j++)    // c2 = tx + 8j: 16B lane stride
                b[j].f = *(const float4*)&X2s[kk][(tx + 8 * j) * BCH];
            #pragma unroll
            for (int i = 0; i < 4; i++)
                #pragma unroll
                for (int j = 0; j < 4; j++) {
                    FMA2(acc[i][j][0], a[i].u[0], b[j].u[0]);
                    FMA2(acc[i][j][1], a[i].u[1], b[j].u[1]);
                }
        }
    }

    // stores: batch-minor 16B per (c1,c2) product
    #pragma unroll
    for (int i = 0; i < 4; i++) {
        int c1 = c1_base + ty + 32 * i;
        #pragma unroll
        for (int j = 0; j < 4; j++) {
            int c2 = c2_base + tx + 8 * j;
            V4 v;
            v.u[0] = acc[i][j][0];
            v.u[1] = acc[i][j][1];
            *(float4*)&M_t[((size_t)c1 * C + c2) * BATCH + bbase] = v.f;
        }
    }
}

// ---------- phase 2: gather-reduce per bucket (no atomics) ----------
// warp per bucket, lane = batch. Each pair: one coalesced 128B load.
__global__ __launch_bounds__(256)
void k_gather(float* __restrict__ out)
{
    const int lane = threadIdx.x & 31;
    const int d = blockIdx.x * 8 + (threadIdx.x >> 5);

    const int pstart = g_off[d];
    const int pend   = g_off[d + 1];

    float acc = 0.0f;
    for (int p = pstart; p < pend; ++p) {
        unsigned int entry = g_pairs[p];              // warp-uniform
        acc += M_t[(size_t)entry * BATCH + lane];     // coalesced 128B
    }
    out[(size_t)lane * D + d] = acc;
}

extern "C" void kernel_launch(void* const* d_in, const int* in_sizes, int n_in,
                              void* d_out, int out_size)
{
    const float* x1 = (const float*)d_in[0];   // bottom1 [32,14,14,512]
    const float* x2 = (const float*)d_in[1];   // bottom2 [32,14,14,512]
    const float* s1 = (const float*)d_in[2];   // rand_s_1 [512]
    const float* s2 = (const float*)d_in[3];   // rand_s_2 [512]
    const int*   h1 = (const int*)d_in[4];     // rand_h_1 [512]
    const int*   h2 = (const int*)d_in[5];     // rand_h_2 [512]
    float* out = (float*)d_out;                // [32, 8192] float32

    // bucket the sparse scatter pattern (one thread per pair)
    k_zero_hist<<<D / 256, 256>>>();
    k_count<<<C * C / 256, 256>>>(h1, h2);
    k_scan<<<1, 256>>>();
    k_fill<<<C * C / 256, 256>>>(h1, h2);

    // batched GEMM into M_t
    dim3 grid(C / 128, C / 32, BATCH / BCH);   // (4, 16, 8) = 512 CTAs
    k_gemm<<<grid, 256>>>(x1, x2, s1, s2);

    // per-bucket gather-reduce into the output
    k_gather<<<D / 8, 256>>>(out);
}

// round 8
// speedup vs baseline: 1.9296x; 1.0518x over previous
#include <cuda_runtime.h>

// Problem constants (fixed by the dataset)
#define BATCH 32
#define HW    196      // 14*14 spatial positions
#define C     512      // input channels
#define D     8192     // sketch / output dimension
#define KT    14       // K-chunk for shared tiles (196 = 14*14)
#define BCH   4        // batches per GEMM CTA
#define PAD   128      // max pairs tracked per bucket (mean 32, P(>128)~1e-40)

typedef unsigned long long ull;

// Scratch: M_t[c1][c2][b] batch-minor so the phase-2 gather (lane = batch)
// reads one coalesced 128B line per pair.
__device__ __align__(16) float M_t[(size_t)C * C * BATCH];   // 33.5 MB
__device__ int          g_cnt[D];
__device__ unsigned int g_table[D * PAD];   // bucket -> list of c1*512+c2

// Packed fp32x2 FMA (Blackwell)
#define FMA2(acc, a2, b2) \
    asm("fma.rn.f32x2 %0, %1, %2, %0;" : "+l"(acc) : "l"(a2), "l"(b2))
#define PACK2(o, lo, hi) \
    asm("mov.b64 %0, {%1, %2};" : "=l"(o) : "f"(lo), "f"(hi))
#define UNPACK2(lo, hi, in) \
    asm("mov.b64 {%0, %1}, %2;" : "=f"(lo), "=f"(hi) : "l"(in))

// ---------- phase 0: bucket the (c1,c2) pairs (2 kernels, ~9us) ----------

__global__ void k_zero_cnt()
{
    int i = blockIdx.x * blockDim.x + threadIdx.x;
    if (i < D) g_cnt[i] = 0;
}

// one thread per (c1,c2) pair
__global__ void k_bucket(const int* __restrict__ h1, const int* __restrict__ h2)
{
    int gid = blockIdx.x * blockDim.x + threadIdx.x;
    int c1 = gid >> 9, c2 = gid & (C - 1);
    int d = (__ldg(&h1[c1]) + __ldg(&h2[c2])) & (D - 1);
    int pos = atomicAdd(&g_cnt[d], 1);
    if (pos < PAD) g_table[d * PAD + pos] = (unsigned int)(c1 * C + c2);
}

// ---------- phase 1: batched GEMM -> M_t (no atomics) ----------
// Tile: c1 128 x c2 32 x batch 4. grid (4, 16, 8) = 512 CTAs, 256 threads.
// Thread (tx = tid&7 -> c2, ty = tid>>3 -> c1): 4 c1 x 4 c2 x 4 batches.
// Batch pairs ride the fp32x2 lanes. Register discipline: a-fragments are
// loaded per-i and die after 4 products; tile loader is unroll-1 so at most
// one float4 assembly is in flight. Peak ~100 regs -> no spill at the
// 128-reg cap from __launch_bounds__(256, 2).
__global__ __launch_bounds__(256, 2)
void k_gemm(const float* __restrict__ x1, const float* __restrict__ x2,
            const float* __restrict__ s1, const float* __restrict__ s2)
{
    __shared__ float X1s[KT][128 * BCH];   // [kk][c1*4 + b]  28 KB
    __shared__ float X2s[KT][32 * BCH];    // [kk][c2*4 + b]   7 KB

    const int tid = threadIdx.x;
    const int tx  = tid & 7;             // c2 lane
    const int ty  = tid >> 3;            // c1 lane (0..31)
    const int c1_base = blockIdx.x * 128;
    const int c2_base = blockIdx.y * 32;
    const int bbase   = blockIdx.z * BCH;

    const size_t bstr = (size_t)HW * C;  // batch stride (elements)

    const int   l1c = tid & 127;         // X1 loader channel (const/thread)
    const float s1l = __ldg(&s1[c1_base + l1c]);
    const int   l2c = tid & 31;          // X2 loader channel
    const float s2l = __ldg(&s2[c2_base + l2c]);

    const float* p1base = x1 + (size_t)bbase * bstr + c1_base + l1c;
    const float* p2base = x2 + (size_t)bbase * bstr + c2_base + l2c;

    ull acc[4][4][2];                    // [c1 i][c2 j][batch pair] = 64 regs
    #pragma unroll
    for (int i = 0; i < 4; i++)
        #pragma unroll
        for (int j = 0; j < 4; j++) { acc[i][j][0] = 0ULL; acc[i][j][1] = 0ULL; }

    for (int k0 = 0; k0 < HW; k0 += KT) {
        __syncthreads();
        // X1 tile: 14*128 slots / 256 threads = 7 float4 per thread
        #pragma unroll 1
        for (int n = 0; n < 7; ++n) {
            int idx = tid + 256 * n;
            int kk  = idx >> 7;
            const float* p = p1base + (size_t)(k0 + kk) * C;
            float4 v;
            v.x = p[0]        * s1l;  v.y = p[bstr]     * s1l;
            v.z = p[2 * bstr] * s1l;  v.w = p[3 * bstr] * s1l;
            *(float4*)&X1s[kk][l1c * BCH] = v;     // 16B lane stride: N=1
        }
        // X2 tile: 14*32 slots, 2 rounds (2nd partial)
        #pragma unroll 1
        for (int n = 0; n < 2; ++n) {
            int idx = tid + 256 * n;
            if (idx < KT * 32) {
                int kk = idx >> 5;
                const float* p = p2base + (size_t)(k0 + kk) * C;
                float4 v;
                v.x = p[0]        * s2l;  v.y = p[bstr]     * s2l;
                v.z = p[2 * bstr] * s2l;  v.w = p[3 * bstr] * s2l;
                *(float4*)&X2s[kk][l2c * BCH] = v;
            }
        }
        __syncthreads();

        #pragma unroll
        for (int kk = 0; kk < KT; ++kk) {
            // b fragments: 4 x fp32x2-pair, live across the i loop (16 regs)
            ull b2[4][2];
            #pragma unroll
            for (int j = 0; j < 4; j++) {   // c2 = tx + 8j: 128B line, N=1
                float4 bv = *(const float4*)&X2s[kk][(tx + 8 * j) * BCH];
                PACK2(b2[j][0], bv.x, bv.y);
                PACK2(b2[j][1], bv.z, bv.w);
            }
            #pragma unroll
            for (int i = 0; i < 4; i++) {   // a fragment dies after 8 FMA2
                float4 av = *(const float4*)&X1s[kk][(ty + 32 * i) * BCH];
                ull a0, a1;
                PACK2(a0, av.x, av.y);
                PACK2(a1, av.z, av.w);
                #pragma unroll
                for (int j = 0; j < 4; j++) {
                    FMA2(acc[i][j][0], a0, b2[j][0]);
                    FMA2(acc[i][j][1], a1, b2[j][1]);
                }
            }
        }
    }

    // stores: batch-minor 16B per (c1,c2) product; 32 distinct 128B lines
    // per warp per (i,j) step -> fully-written sectors
    #pragma unroll
    for (int i = 0; i < 4; i++) {
        int c1 = c1_base + ty + 32 * i;
        #pragma unroll
        for (int j = 0; j < 4; j++) {
            int c2 = c2_base + tx + 8 * j;
            float4 v;
            UNPACK2(v.x, v.y, acc[i][j][0]);
            UNPACK2(v.z, v.w, acc[i][j][1]);
            *(float4*)&M_t[((size_t)c1 * C + c2) * BATCH + bbase] = v;
        }
    }
}

// ---------- phase 2: gather-reduce per bucket (no atomics) ----------
// warp per bucket, lane = batch. Each pair: one coalesced 128B load.
__global__ __launch_bounds__(256)
void k_gather(float* __restrict__ out)
{
    const int lane = threadIdx.x & 31;
    const int d = blockIdx.x * 8 + (threadIdx.x >> 5);

    const unsigned int* tab = &g_table[d * PAD];
    const int n = g_cnt[d];

    float acc = 0.0f;
    for (int p = 0; p < n; ++p) {
        unsigned int entry = __ldg(&tab[p]);          // warp-uniform
        acc += M_t[(size_t)entry * BATCH + lane];     // coalesced 128B
    }
    out[(size_t)lane * D + d] = acc;
}

extern "C" void kernel_launch(void* const* d_in, const int* in_sizes, int n_in,
                              void* d_out, int out_size)
{
    const float* x1 = (const float*)d_in[0];   // bottom1 [32,14,14,512]
    const float* x2 = (const float*)d_in[1];   // bottom2 [32,14,14,512]
    const float* s1 = (const float*)d_in[2];   // rand_s_1 [512]
    const float* s2 = (const float*)d_in[3];   // rand_s_2 [512]
    const int*   h1 = (const int*)d_in[4];     // rand_h_1 [512]
    const int*   h2 = (const int*)d_in[5];     // rand_h_2 [512]
    float* out = (float*)d_out;                // [32, 8192] float32

    // bucket the sparse scatter pattern (one thread per pair)
    k_zero_cnt<<<D / 256, 256>>>();
    k_bucket<<<C * C / 256, 256>>>(h1, h2);

    // batched GEMM into M_t
    dim3 grid(C / 128, C / 32, BATCH / BCH);   // (4, 16, 8) = 512 CTAs
    k_gemm<<<grid, 256>>>(x1, x2, s1, s2);

    // per-bucket gather-reduce into the output
    k_gather<<<D / 8, 256>>>(out);
}

// round 11
// speedup vs baseline: 3.3561x; 1.7393x over previous
#include <cuda_runtime.h>

// Problem constants (fixed by the dataset)
#define BATCH 32
#define HW    196      // 14*14 spatial positions
#define C     512      // input channels
#define D     8192     // sketch / output dimension
#define KT    14       // K-chunk for shared tiles (196 = 14*14)
#define C2T   2        // c2-tiles processed per CTA (x1 slice turns L1-hot)

typedef unsigned long long ull;

// Packed fp32x2 FMA (Blackwell): acc = a2 * b2 + acc  (2 independent FMAs)
#define FMA2(acc, a2, b2) \
    asm("fma.rn.f32x2 %0, %1, %2, %0;" : "+l"(acc) : "l"(a2), "l"(b2))
#define PACK2(o, lo, hi) \
    asm("mov.b64 %0, {%1, %2};" : "=l"(o) : "f"(lo), "f"(hi))
#define UNPACK2(lo, hi, in) \
    asm("mov.b64 {%0, %1}, %2;" : "=f"(lo), "=f"(hi) : "l"(in))

// result-less shared-memory reduction (REDS path, no ATOMS return)
__device__ __forceinline__ void red_shared_add(float* p, float v)
{
    unsigned int a = (unsigned int)__cvta_generic_to_shared(p);
    asm volatile("red.shared.add.f32 [%0], %1;" :: "r"(a), "f"(v) : "memory");
}

// Fused kernel:
//   grid (4, 2, 32): blockIdx.x = c1 tile (128), blockIdx.y = c2 super-tile
//   (256 = 2 x 128 processed in-CTA), blockIdx.z = batch.
//   256 threads, 8x8 scalar accumulators per thread as 8 x 4 fp32x2.
// For each of the 2 c2-tiles: GEMM the 128x128 tile of M[b] = X1^T X2
// (signs folded into the shared tiles), scatter products into the
// block-private smem copy of out[b,:] at bucket (h1+h2) & 8191.
// outacc is zeroed once and flushed once per CTA. The x1 slice is re-read
// on the 2nd c2-tile from L1 (100KB slice, L1-resident), halving x1 L2
// traffic vs one-tile CTAs.
__global__ __launch_bounds__(256, 2)
void cbp_fused(const float* __restrict__ x1, const float* __restrict__ x2,
               const float* __restrict__ s1, const float* __restrict__ s2,
               const int*   __restrict__ h1, const int*   __restrict__ h2,
               float* __restrict__ out)
{
    __shared__ float X1s[KT][128];
    __shared__ float X2s[KT][128];
    __shared__ float outacc[D];          // 32 KB block-private accumulator

    const int tid = threadIdx.x;
    const int tx  = tid & 15;            // c2 direction
    const int ty  = tid >> 4;            // c1 direction
    const int b   = blockIdx.z;
    const int c1_base = blockIdx.x * 128;

    // zero private accumulator (once per CTA)
    #pragma unroll
    for (int i = tid; i < D; i += 256) outacc[i] = 0.0f;

    const float* X1 = x1 + (size_t)b * HW * C;
    const float* X2 = x2 + (size_t)b * HW * C;

    const int   lc  = tid & 127;         // loader channel (constant/thread)
    const float s1l = __ldg(&s1[c1_base + lc]);

    int h1v[8];
    #pragma unroll
    for (int i = 0; i < 8; i++) {
        int c1 = c1_base + ((i < 4) ? (ty * 4 + i) : (64 + ty * 4 + i - 4));
        h1v[i] = __ldg(&h1[c1]);
    }

    #pragma unroll 1
    for (int t = 0; t < C2T; ++t) {
        const int c2_base = blockIdx.y * (128 * C2T) + t * 128;
        const float s2l = __ldg(&s2[c2_base + lc]);

        // 8 rows x 4 packed-column-pairs of fp32x2 accumulators
        ull accp[8][4];
        #pragma unroll
        for (int i = 0; i < 8; i++)
            #pragma unroll
            for (int j = 0; j < 4; j++) accp[i][j] = 0ULL;

        for (int k0 = 0; k0 < HW; k0 += KT) {
            __syncthreads();   // protect tiles from previous readers
            #pragma unroll
            for (int n = 0; n < (KT * 128) / 256; ++n) {   // 7 per tensor
                int idx = tid + n * 256;
                int kk  = idx >> 7;
                X1s[kk][lc] = X1[(k0 + kk) * C + c1_base + lc] * s1l;
                X2s[kk][lc] = X2[(k0 + kk) * C + c2_base + lc] * s2l;
            }
            __syncthreads();

            #pragma unroll
            for (int kk = 0; kk < KT; ++kk) {
                float4 a0 = *(const float4*)&X1s[kk][ty * 4];
                float4 a1 = *(const float4*)&X1s[kk][64 + ty * 4];
                float4 b0 = *(const float4*)&X2s[kk][tx * 4];
                float4 b1 = *(const float4*)&X2s[kk][64 + tx * 4];

                ull bv2[4];
                PACK2(bv2[0], b0.x, b0.y);
                PACK2(bv2[1], b0.z, b0.w);
                PACK2(bv2[2], b1.x, b1.y);
                PACK2(bv2[3], b1.z, b1.w);

                float av[8] = {a0.x, a0.y, a0.z, a0.w,
                               a1.x, a1.y, a1.z, a1.w};
                #pragma unroll
                for (int i = 0; i < 8; i++) {
                    ull a2;
                    PACK2(a2, av[i], av[i]);
                    #pragma unroll
                    for (int j = 0; j < 4; j++)
                        FMA2(accp[i][j], a2, bv2[j]);
                }
            }
        }

        // ---- scatter this tile into the block-private accumulator ----
        int h2v[8];
        #pragma unroll
        for (int j = 0; j < 8; j++) {
            int c2 = c2_base + ((j < 4) ? (tx * 4 + j)
                                        : (64 + tx * 4 + j - 4));
            h2v[j] = __ldg(&h2[c2]);
        }

        #pragma unroll
        for (int i = 0; i < 8; i++) {
            #pragma unroll
            for (int j2 = 0; j2 < 4; j2++) {
                float vlo, vhi;
                UNPACK2(vlo, vhi, accp[i][j2]);
                int dlo = (h1v[i] + h2v[2 * j2])     & (D - 1);
                int dhi = (h1v[i] + h2v[2 * j2 + 1]) & (D - 1);
                red_shared_add(&outacc[dlo], vlo);
                red_shared_add(&outacc[dhi], vhi);
            }
        }
    }

    __syncthreads();
    // ---- flush private accumulator to global output (once per CTA) ----
    float* outb = out + (size_t)b * D;
    #pragma unroll
    for (int i = tid; i < D; i += 256) {
        float v = outacc[i];
        if (v != 0.0f) atomicAdd(&outb[i], v);   // result unused -> REDG
    }
}

__global__ void zero_out_kernel(float* __restrict__ out, int n)
{
    int i = blockIdx.x * blockDim.x + threadIdx.x;
    if (i < n) out[i] = 0.0f;
}

extern "C" void kernel_launch(void* const* d_in, const int* in_sizes, int n_in,
                              void* d_out, int out_size)
{
    const float* x1 = (const float*)d_in[0];   // bottom1 [32,14,14,512]
    const float* x2 = (const float*)d_in[1];   // bottom2 [32,14,14,512]
    const float* s1 = (const float*)d_in[2];   // rand_s_1 [512]
    const float* s2 = (const float*)d_in[3];   // rand_s_2 [512]
    const int*   h1 = (const int*)d_in[4];     // rand_h_1 [512]
    const int*   h2 = (const int*)d_in[5];     // rand_h_2 [512]
    float* out = (float*)d_out;                // [32, 8192] float32

    const int n = BATCH * D;
    zero_out_kernel<<<(n + 255) / 256, 256>>>(out, n);

    dim3 grid(C / 128, C / (128 * C2T), BATCH);   // (4, 2, 32) = 256 CTAs
    cbp_fused<<<grid, 256>>>(x1, x2, s1, s2, h1, h2, out);
}